// round 15
// baseline (speedup 1.0000x reference)
#include <cuda_runtime.h>
#include <cuda_bf16.h>
#include <math.h>

#define IN_CH    4
#define OUT_CH   8
#define KW       8
#define N_LAYERS 2
#define N_IN     32
#define N_QUBITS 7
#define QDIM     128
#define BATCH    16
#define LIN      2048
#define LOUT     (LIN - KW + 1)   // 2041
#define NGATES   (N_LAYERS * N_QUBITS)

// Quadratic-form matrices, symmetric-packed, in the constant bank:
//   B[o][i][j] = 0 (j<i), A_ii (j==i), 2*A_ij (j>i)
__constant__ float4 c_B[OUT_CH * N_IN * N_IN / 4];

// ---------------------------------------------------------------------------
// build kernel: grid (16 i-groups, 8 out-ch) = 128 blocks, 256 threads.
// Simulates the 32 basis columns of its o, computes 2 rows of A with 4 warps
// per row, reduces in shared, writes symmetric-packed B directly to the
// constant backing. Triggers PDL completion at start.
// ---------------------------------------------------------------------------
__global__ __launch_bounds__(256, 1)
void build_kernel(const float* __restrict__ thetas, float* __restrict__ cB) {
    __shared__ float sU[NGATES][8];
    __shared__ float2 sT[QDIM * 33];     // [m][j] (re,im)
    __shared__ float sP[8][33];          // per-warp partial rows

    if (threadIdx.x == 0) cudaTriggerProgrammaticLaunchCompletion();

    const int ig = blockIdx.x;           // rows 2*ig, 2*ig+1
    const int o  = blockIdx.y;
    const int tid  = threadIdx.x;
    const int warp = tid >> 5;
    const int lane = tid & 31;

    if (tid < NGATES) {
        const float* th = thetas + (o * NGATES + tid) * 3;
        float a = th[0], b = th[1], g = th[2];
        float sb, cb; __sincosf(0.5f * b, &sb, &cb);
        float sp, cp; __sincosf(0.5f * (a + g), &sp, &cp);   // ep
        float sm, cm; __sincosf(0.5f * (a - g), &sm, &cm);   // em
        sU[tid][0] =  cp * cb;  sU[tid][1] = -sp * cb;       // u00 = conj(ep)*cb
        sU[tid][2] = -cm * sb;  sU[tid][3] =  sm * sb;       // u01 = -conj(em)*sb
        sU[tid][4] =  cm * sb;  sU[tid][5] =  sm * sb;       // u10 = em*sb
        sU[tid][6] =  cp * cb;  sU[tid][7] =  sp * cb;       // u11 = ep*cb
    }
    __syncthreads();

    float re[4][4], im[4][4];
#pragma unroll
    for (int c = 0; c < 4; c++)
#pragma unroll
        for (int r = 0; r < 4; r++) { re[c][r] = 0.f; im[c][r] = 0.f; }
#pragma unroll
    for (int c = 0; c < 4; c++)
        if (lane == 4 * warp + c) re[c][0] = 1.0f;

    for (int l = 0; l < N_LAYERS; l++) {
#pragma unroll
        for (int q = 0; q < N_QUBITS; q++) {
            const float* U = sU[l * N_QUBITS + q];
            float u00r = U[0], u00i = U[1], u01r = U[2], u01i = U[3];
            float u10r = U[4], u10i = U[5], u11r = U[6], u11i = U[7];
            int p = 6 - q;
            if (p >= 5) {
                int d = 1 << (p - 5);
#pragma unroll
                for (int c = 0; c < 4; c++)
#pragma unroll
                    for (int r0 = 0; r0 < 4; r0++) {
                        if (r0 & d) continue;
                        int r1 = r0 | d;
                        float a0r = re[c][r0], a0i = im[c][r0];
                        float a1r = re[c][r1], a1i = im[c][r1];
                        re[c][r0] = u00r*a0r - u00i*a0i + u01r*a1r - u01i*a1i;
                        im[c][r0] = u00r*a0i + u00i*a0r + u01r*a1i + u01i*a1r;
                        re[c][r1] = u10r*a0r - u10i*a0i + u11r*a1r - u11i*a1i;
                        im[c][r1] = u10r*a0i + u10i*a0r + u11r*a1i + u11i*a1r;
                    }
            } else {
                int mask = 1 << p;
                int bit = (lane >> p) & 1;
#pragma unroll
                for (int c = 0; c < 4; c++)
#pragma unroll
                    for (int r = 0; r < 4; r++) {
                        float otr = __shfl_xor_sync(0xffffffffu, re[c][r], mask);
                        float oti = __shfl_xor_sync(0xffffffffu, im[c][r], mask);
                        float sr = re[c][r], si = im[c][r];
                        if (bit == 0) {
                            re[c][r] = u00r*sr - u00i*si + u01r*otr - u01i*oti;
                            im[c][r] = u00r*si + u00i*sr + u01r*oti + u01i*otr;
                        } else {
                            re[c][r] = u10r*otr - u10i*oti + u11r*sr - u11i*si;
                            im[c][r] = u10r*oti + u10i*otr + u11r*si + u11i*sr;
                        }
                    }
            }
        }
#pragma unroll
        for (int r = 0; r < 4; r++) {
            int m = lane + 32 * r;
            int k = __popc(m);
            if (((k * (k - 1)) >> 1) & 1) {
#pragma unroll
                for (int c = 0; c < 4; c++) { re[c][r] = -re[c][r]; im[c][r] = -im[c][r]; }
            }
        }
    }

#pragma unroll
    for (int c = 0; c < 4; c++) {
        int j = 4 * warp + c;
#pragma unroll
        for (int r = 0; r < 4; r++) {
            int m = lane + 32 * r;
            sT[m * 33 + j] = make_float2(re[c][r], im[c][r]);
        }
    }
    __syncthreads();

    {
        const int r  = warp >> 2;
        const int qm = (warp & 3) * 32;
        const int i  = ig * 2 + r;
        const int j  = lane;
        float s0 = 0.f, s1 = 0.f;
#pragma unroll
        for (int mm = 0; mm < 32; mm += 2) {
            int m = qm + mm;
            float2 ci0 = sT[m*33 + i],     cj0 = sT[m*33 + j];
            float2 ci1 = sT[(m+1)*33 + i], cj1 = sT[(m+1)*33 + j];
            s0 += ci0.x * cj0.x + ci0.y * cj0.y;
            s1 += ci1.x * cj1.x + ci1.y * cj1.y;
        }
        float s = s0 + s1;
        sP[warp][lane] = (qm < 64) ? s : -s;
    }
    __syncthreads();

    if (tid < 64) {
        const int r = tid >> 5, j = tid & 31;
        const int i = ig * 2 + r;
        float s = sP[4*r + 0][j] + sP[4*r + 1][j] + sP[4*r + 2][j] + sP[4*r + 3][j];
        float val = (j < i) ? 0.f : (j == i ? s : 2.f * s);
        cB[(o * N_IN + i) * N_IN + j] = val;
    }
}

// ---------------------------------------------------------------------------
// conv kernel: 512 threads/block, 512 blocks (same grid as R13's best).
// Warp quad (4v..4v+3) covers 32 t-quads; 4-way phase split of the 144
// triangle groups into exact 36/36/36/36 row-pair sets:
//   phase0:{0,2,12,14} phase1:{1,3,13,15} phase2:{4,6,8,10} phase3:{5,7,9,11}
// Phases 0-2 store partials; phase 3 combines + epilogue. PDL prologue
// (x staging, window unpack, norms) runs before cudaGridDependencySynchronize.
// ---------------------------------------------------------------------------
#define NTHR   512
#define TILE_T 512
#define XROW   520                 // 512 + KW, mult of 4 -> 16B-aligned rows

#define XV(j,dt) xv[(j) >> 3][((j) & 7) + (dt)]

__global__ __launch_bounds__(NTHR)
void conv_kernel(const float* __restrict__ x, float* __restrict__ out) {
    __shared__ alignas(16) float xs[IN_CH][XROW];
    __shared__ alignas(16) float4 sAcc[3][128];
    __shared__ alignas(16) float4 sN2[128];

    const int b  = blockIdx.y;
    const int o  = blockIdx.z;
    const int t0 = blockIdx.x * TILE_T;
    const int tid = threadIdx.x;

    for (int idx = tid; idx < IN_CH * (TILE_T + KW); idx += NTHR) {
        int c = idx / (TILE_T + KW), i = idx % (TILE_T + KW);
        int gi = t0 + i;
        xs[c][i] = (gi < LIN) ? x[(b * IN_CH + c) * LIN + gi] : 0.f;
    }
    __syncthreads();

    const int warp  = tid >> 5;
    const int lane  = tid & 31;
    const int u     = (warp >> 2) * 32 + lane;   // t-quad index 0..127
    const int phase = warp & 3;                  // warp-uniform

    // xv[c][0..10]: window for dt is w[c*8+k] = xv[c][k+dt], dt = 0..3
    float xv[IN_CH][12];
#pragma unroll
    for (int c = 0; c < IN_CH; c++) {
        const float4* xr = reinterpret_cast<const float4*>(&xs[c][4 * u]);
        float4 v0 = xr[0], v1 = xr[1], v2 = xr[2];
        xv[c][0]=v0.x; xv[c][1]=v0.y; xv[c][2] =v0.z; xv[c][3] =v0.w;
        xv[c][4]=v1.x; xv[c][5]=v1.y; xv[c][6] =v1.z; xv[c][7] =v1.w;
        xv[c][8]=v2.x; xv[c][9]=v2.y; xv[c][10]=v2.z; xv[c][11]=v2.w;
    }

    // window norms (independent of B) — phase0 computes before the sync
    if (phase == 0) {
        float n2[4];
        float s = 0.f;
#pragma unroll
        for (int c = 0; c < IN_CH; c++)
#pragma unroll
            for (int k = 0; k < KW; k++) { float v = xv[c][k]; s += v * v; }
        n2[0] = s;
#pragma unroll
        for (int dt = 1; dt < 4; dt++) {
            float d = 0.f;
#pragma unroll
            for (int c = 0; c < IN_CH; c++) {
                float vn = xv[c][dt + 7], vo = xv[c][dt - 1];
                d += vn * vn - vo * vo;
            }
            n2[dt] = n2[dt - 1] + d;
        }
        sN2[u] = make_float4(n2[0], n2[1], n2[2], n2[3]);
    }

    // wait for build_kernel (PDL)
    cudaGridDependencySynchronize();

    const int obase = o * (N_IN * N_IN / 4);   // warp-uniform
    float acc[4] = {0.f, 0.f, 0.f, 0.f};

#define PROCESS_PAIR(ip_)                                                    \
    {                                                                        \
        const int ibq = (ip_) >> 1;                                          \
        float s0[4] = {0.f,0.f,0.f,0.f}, s1[4] = {0.f,0.f,0.f,0.f};          \
        _Pragma("unroll")                                                    \
        for (int j4 = ibq; j4 < 8; j4++) {                                   \
            float4 a0 = c_B[obase + (2*(ip_)    ) * 8 + j4];                 \
            float4 a1 = c_B[obase + (2*(ip_) + 1) * 8 + j4];                 \
            const int j0 = 4 * j4;                                           \
            _Pragma("unroll")                                                \
            for (int dt = 0; dt < 4; dt++) {                                 \
                float w0 = XV(j0, dt),   w1 = XV(j0+1, dt);                  \
                float w2 = XV(j0+2, dt), w3 = XV(j0+3, dt);                  \
                s0[dt] += a0.x*w0 + a0.y*w1 + a0.z*w2 + a0.w*w3;             \
                s1[dt] += a1.x*w0 + a1.y*w1 + a1.z*w2 + a1.w*w3;             \
            }                                                                \
        }                                                                    \
        _Pragma("unroll")                                                    \
        for (int dt = 0; dt < 4; dt++) {                                     \
            acc[dt] += s0[dt] * XV(2*(ip_),     dt);                         \
            acc[dt] += s1[dt] * XV(2*(ip_) + 1, dt);                         \
        }                                                                    \
    }

    // balanced 36/36/36/36 group split over row pairs
    if (phase == 0) {
        PROCESS_PAIR(0) PROCESS_PAIR(2) PROCESS_PAIR(12) PROCESS_PAIR(14)
        sAcc[0][u] = make_float4(acc[0], acc[1], acc[2], acc[3]);
    } else if (phase == 1) {
        PROCESS_PAIR(1) PROCESS_PAIR(3) PROCESS_PAIR(13) PROCESS_PAIR(15)
        sAcc[1][u] = make_float4(acc[0], acc[1], acc[2], acc[3]);
    } else if (phase == 2) {
        PROCESS_PAIR(4) PROCESS_PAIR(6) PROCESS_PAIR(8) PROCESS_PAIR(10)
        sAcc[2][u] = make_float4(acc[0], acc[1], acc[2], acc[3]);
    } else {
        PROCESS_PAIR(5) PROCESS_PAIR(7) PROCESS_PAIR(9) PROCESS_PAIR(11)
    }

    __syncthreads();

    if (phase == 3) {
        float4 p0 = sAcc[0][u], p1 = sAcc[1][u], p2 = sAcc[2][u];
        float4 nn = sN2[u];
        acc[0] += p0.x + p1.x + p2.x;
        acc[1] += p0.y + p1.y + p2.y;
        acc[2] += p0.z + p1.z + p2.z;
        acc[3] += p0.w + p1.w + p2.w;
        float nv[4] = {nn.x, nn.y, nn.z, nn.w};

        float* po = out + (b * OUT_CH + o) * LOUT;
        const int tb = t0 + 4 * u;
#pragma unroll
        for (int dt = 0; dt < 4; dt++) {
            int t = tb + dt;
            if (t < LOUT) po[t] = acc[dt] * __fdividef(1.0f, nv[dt]);
        }
    }
}

// ---------------------------------------------------------------------------
extern "C" void kernel_launch(void* const* d_in, const int* in_sizes, int n_in,
                              void* d_out, int out_size) {
    const float* x      = (const float*)d_in[0];   // (16, 4, 2048) f32
    const float* thetas = (const float*)d_in[1];   // (8, 2, 7, 3) f32
    float* out = (float*)d_out;                    // (16, 8, 2041) f32

    void* pC = nullptr;
    cudaGetSymbolAddress(&pC, c_B);

    dim3 bgrid(16, OUT_CH);                        // 128 blocks
    build_kernel<<<bgrid, 256>>>(thetas, (float*)pC);

    // conv with programmatic dependent launch: prologue overlaps build
    cudaLaunchConfig_t cfg = {};
    cfg.gridDim  = dim3((LOUT + TILE_T - 1) / TILE_T, BATCH, OUT_CH);  // 4x16x8
    cfg.blockDim = dim3(NTHR, 1, 1);
    cfg.dynamicSmemBytes = 0;
    cfg.stream = 0;
    cudaLaunchAttribute attr;
    attr.id = cudaLaunchAttributeProgrammaticStreamSerialization;
    attr.val.programmaticStreamSerializationAllowed = 1;
    cfg.attrs = &attr;
    cfg.numAttrs = 1;
    cudaLaunchKernelEx(&cfg, conv_kernel, x, out);
}

// round 16
// speedup vs baseline: 1.6386x; 1.6386x over previous
#include <cuda_runtime.h>
#include <cuda_bf16.h>
#include <math.h>

#define IN_CH    4
#define OUT_CH   8
#define KW       8
#define N_LAYERS 2
#define N_IN     32
#define N_QUBITS 7
#define QDIM     128
#define BATCH    16
#define LIN      2048
#define LOUT     (LIN - KW + 1)   // 2041
#define NGATES   (N_LAYERS * N_QUBITS)

// Quadratic-form matrices, symmetric-packed, in the constant bank:
//   B[o][i][j] = 0 (j<i), A_ii (j==i), 2*A_ij (j>i)
// build_kernel writes DIRECTLY to this symbol's device address.
__constant__ float4 c_B[OUT_CH * N_IN * N_IN / 4];

// ---------------------------------------------------------------------------
// build kernel: grid (16 i-groups, 8 out-ch) = 128 blocks, 256 threads.
// Each block simulates the 32 basis columns of its o, then computes 2 rows
// of A with 4 warps per row (32 m each, z0 sign folded), reducing in shared.
// Triggers PDL completion at start so conv can launch concurrently.
// ---------------------------------------------------------------------------
__global__ __launch_bounds__(256, 1)
void build_kernel(const float* __restrict__ thetas, float* __restrict__ cB) {
    __shared__ float sU[NGATES][8];
    __shared__ float2 sT[QDIM * 33];     // [m][j] (re,im)
    __shared__ float sP[8][33];          // per-warp partial rows

    if (threadIdx.x == 0) cudaTriggerProgrammaticLaunchCompletion();

    const int ig = blockIdx.x;           // rows 2*ig, 2*ig+1
    const int o  = blockIdx.y;
    const int tid  = threadIdx.x;
    const int warp = tid >> 5;
    const int lane = tid & 31;

    if (tid < NGATES) {
        const float* th = thetas + (o * NGATES + tid) * 3;
        float a = th[0], b = th[1], g = th[2];
        float sb, cb; __sincosf(0.5f * b, &sb, &cb);
        float sp, cp; __sincosf(0.5f * (a + g), &sp, &cp);   // ep
        float sm, cm; __sincosf(0.5f * (a - g), &sm, &cm);   // em
        sU[tid][0] =  cp * cb;  sU[tid][1] = -sp * cb;       // u00 = conj(ep)*cb
        sU[tid][2] = -cm * sb;  sU[tid][3] =  sm * sb;       // u01 = -conj(em)*sb
        sU[tid][4] =  cm * sb;  sU[tid][5] =  sm * sb;       // u10 = em*sb
        sU[tid][6] =  cp * cb;  sU[tid][7] =  sp * cb;       // u11 = ep*cb
    }
    __syncthreads();

    // warp simulates columns j = 4*warp + c; amps m = lane + 32*r.
    float re[4][4], im[4][4];
#pragma unroll
    for (int c = 0; c < 4; c++)
#pragma unroll
        for (int r = 0; r < 4; r++) { re[c][r] = 0.f; im[c][r] = 0.f; }
#pragma unroll
    for (int c = 0; c < 4; c++)
        if (lane == 4 * warp + c) re[c][0] = 1.0f;

    for (int l = 0; l < N_LAYERS; l++) {
#pragma unroll
        for (int q = 0; q < N_QUBITS; q++) {
            const float* U = sU[l * N_QUBITS + q];
            float u00r = U[0], u00i = U[1], u01r = U[2], u01i = U[3];
            float u10r = U[4], u10i = U[5], u11r = U[6], u11i = U[7];
            int p = 6 - q;
            if (p >= 5) {
                int d = 1 << (p - 5);
#pragma unroll
                for (int c = 0; c < 4; c++)
#pragma unroll
                    for (int r0 = 0; r0 < 4; r0++) {
                        if (r0 & d) continue;
                        int r1 = r0 | d;
                        float a0r = re[c][r0], a0i = im[c][r0];
                        float a1r = re[c][r1], a1i = im[c][r1];
                        re[c][r0] = u00r*a0r - u00i*a0i + u01r*a1r - u01i*a1i;
                        im[c][r0] = u00r*a0i + u00i*a0r + u01r*a1i + u01i*a1r;
                        re[c][r1] = u10r*a0r - u10i*a0i + u11r*a1r - u11i*a1i;
                        im[c][r1] = u10r*a0i + u10i*a0r + u11r*a1i + u11i*a1r;
                    }
            } else {
                int mask = 1 << p;
                int bit = (lane >> p) & 1;
#pragma unroll
                for (int c = 0; c < 4; c++)
#pragma unroll
                    for (int r = 0; r < 4; r++) {
                        float otr = __shfl_xor_sync(0xffffffffu, re[c][r], mask);
                        float oti = __shfl_xor_sync(0xffffffffu, im[c][r], mask);
                        float sr = re[c][r], si = im[c][r];
                        if (bit == 0) {
                            re[c][r] = u00r*sr - u00i*si + u01r*otr - u01i*oti;
                            im[c][r] = u00r*si + u00i*sr + u01r*oti + u01i*otr;
                        } else {
                            re[c][r] = u10r*otr - u10i*oti + u11r*sr - u11i*si;
                            im[c][r] = u10r*oti + u10i*otr + u11r*si + u11i*sr;
                        }
                    }
            }
        }
#pragma unroll
        for (int r = 0; r < 4; r++) {
            int m = lane + 32 * r;
            int k = __popc(m);
            if (((k * (k - 1)) >> 1) & 1) {
#pragma unroll
                for (int c = 0; c < 4; c++) { re[c][r] = -re[c][r]; im[c][r] = -im[c][r]; }
            }
        }
    }

#pragma unroll
    for (int c = 0; c < 4; c++) {
        int j = 4 * warp + c;
#pragma unroll
        for (int r = 0; r < 4; r++) {
            int m = lane + 32 * r;
            sT[m * 33 + j] = make_float2(re[c][r], im[c][r]);
        }
    }
    __syncthreads();

    // Phase C: warp w -> row r = w>>2, m-quarter q = w&3 (32 m each).
    {
        const int r  = warp >> 2;
        const int qm = (warp & 3) * 32;
        const int i  = ig * 2 + r;
        const int j  = lane;
        float s0 = 0.f, s1 = 0.f;
#pragma unroll
        for (int mm = 0; mm < 32; mm += 2) {
            int m = qm + mm;
            float2 ci0 = sT[m*33 + i],     cj0 = sT[m*33 + j];
            float2 ci1 = sT[(m+1)*33 + i], cj1 = sT[(m+1)*33 + j];
            s0 += ci0.x * cj0.x + ci0.y * cj0.y;
            s1 += ci1.x * cj1.x + ci1.y * cj1.y;
        }
        float s = s0 + s1;
        sP[warp][lane] = (qm < 64) ? s : -s;
    }
    __syncthreads();

    if (tid < 64) {
        const int r = tid >> 5, j = tid & 31;
        const int i = ig * 2 + r;
        float s = sP[4*r + 0][j] + sP[4*r + 1][j] + sP[4*r + 2][j] + sP[4*r + 3][j];
        float val = (j < i) ? 0.f : (j == i ? s : 2.f * s);
        cB[(o * N_IN + i) * N_IN + j] = val;
    }
}

// ---------------------------------------------------------------------------
// conv kernel (R13 frame): 256 threads; warp pair covers 32 t-quads.
// Phase split 74/70 j4-groups: phase0 = row pairs {0..4, 15} (74 groups),
// phase1 = {5..14} (70 groups) + combine + epilogue — phase1's extra
// epilogue work offset by 4 fewer groups. PDL prologue before gridsync.
// ---------------------------------------------------------------------------
#define NTHR   256
#define TILE_T 512
#define XROW   520                 // 512 + KW, mult of 4 -> 16B-aligned rows

#define XV(j,dt) xv[(j) >> 3][((j) & 7) + (dt)]

__global__ __launch_bounds__(NTHR)
void conv_kernel(const float* __restrict__ x, float* __restrict__ out) {
    __shared__ alignas(16) float xs[IN_CH][XROW];
    __shared__ alignas(16) float4 sAcc[128];
    __shared__ alignas(16) float4 sN2[128];

    const int b  = blockIdx.y;
    const int o  = blockIdx.z;
    const int t0 = blockIdx.x * TILE_T;
    const int tid = threadIdx.x;

    for (int idx = tid; idx < IN_CH * (TILE_T + KW); idx += NTHR) {
        int c = idx / (TILE_T + KW), i = idx % (TILE_T + KW);
        int gi = t0 + i;
        xs[c][i] = (gi < LIN) ? x[(b * IN_CH + c) * LIN + gi] : 0.f;
    }
    __syncthreads();

    const int warp  = tid >> 5;
    const int lane  = tid & 31;
    const int u     = (warp >> 1) * 32 + lane;   // t-quad index 0..127
    const int phase = warp & 1;                  // warp-uniform

    // xv[c][0..10]: window for dt is w[c*8+k] = xv[c][k+dt], dt = 0..3
    float xv[IN_CH][12];
#pragma unroll
    for (int c = 0; c < IN_CH; c++) {
        const float4* xr = reinterpret_cast<const float4*>(&xs[c][4 * u]);
        float4 v0 = xr[0], v1 = xr[1], v2 = xr[2];
        xv[c][0]=v0.x; xv[c][1]=v0.y; xv[c][2] =v0.z; xv[c][3] =v0.w;
        xv[c][4]=v1.x; xv[c][5]=v1.y; xv[c][6] =v1.z; xv[c][7] =v1.w;
        xv[c][8]=v2.x; xv[c][9]=v2.y; xv[c][10]=v2.z; xv[c][11]=v2.w;
    }

    // window norms (independent of B) — phase0 computes them before the sync
    if (phase == 0) {
        float n2[4];
        float s = 0.f;
#pragma unroll
        for (int c = 0; c < IN_CH; c++)
#pragma unroll
            for (int k = 0; k < KW; k++) { float v = xv[c][k]; s += v * v; }
        n2[0] = s;
#pragma unroll
        for (int dt = 1; dt < 4; dt++) {
            float d = 0.f;
#pragma unroll
            for (int c = 0; c < IN_CH; c++) {
                float vn = xv[c][dt + 7], vo = xv[c][dt - 1];
                d += vn * vn - vo * vo;
            }
            n2[dt] = n2[dt - 1] + d;
        }
        sN2[u] = make_float4(n2[0], n2[1], n2[2], n2[3]);
    }

    // wait for build_kernel (PDL): full completion + memory visibility
    cudaGridDependencySynchronize();

    const int obase = o * (N_IN * N_IN / 4);   // warp-uniform
    float acc[4] = {0.f, 0.f, 0.f, 0.f};

#define PROCESS_PAIR(ip_)                                                    \
    {                                                                        \
        const int ibq = (ip_) >> 1;                                          \
        float s0[4] = {0.f,0.f,0.f,0.f}, s1[4] = {0.f,0.f,0.f,0.f};          \
        _Pragma("unroll")                                                    \
        for (int j4 = ibq; j4 < 8; j4++) {                                   \
            float4 a0 = c_B[obase + (2*(ip_)    ) * 8 + j4];                 \
            float4 a1 = c_B[obase + (2*(ip_) + 1) * 8 + j4];                 \
            const int j0 = 4 * j4;                                           \
            _Pragma("unroll")                                                \
            for (int dt = 0; dt < 4; dt++) {                                 \
                float w0 = XV(j0, dt),   w1 = XV(j0+1, dt);                  \
                float w2 = XV(j0+2, dt), w3 = XV(j0+3, dt);                  \
                s0[dt] += a0.x*w0 + a0.y*w1 + a0.z*w2 + a0.w*w3;             \
                s1[dt] += a1.x*w0 + a1.y*w1 + a1.z*w2 + a1.w*w3;             \
            }                                                                \
        }                                                                    \
        _Pragma("unroll")                                                    \
        for (int dt = 0; dt < 4; dt++) {                                     \
            acc[dt] += s0[dt] * XV(2*(ip_),     dt);                         \
            acc[dt] += s1[dt] * XV(2*(ip_) + 1, dt);                         \
        }                                                                    \
    }

    if (phase == 0) {
        // row pairs {0..4} (72 groups) + {15} (2 groups) = 74
#pragma unroll
        for (int ip = 0; ip < 5; ip++) PROCESS_PAIR(ip)
        PROCESS_PAIR(15)
        sAcc[u] = make_float4(acc[0], acc[1], acc[2], acc[3]);
    } else {
        // row pairs {5..14} = 70 groups, then combine + epilogue
#pragma unroll
        for (int ip = 5; ip < 15; ip++) PROCESS_PAIR(ip)
    }

    __syncthreads();

    if (phase == 1) {
        float4 p  = sAcc[u];
        float4 nn = sN2[u];
        acc[0] += p.x; acc[1] += p.y; acc[2] += p.z; acc[3] += p.w;
        float nv[4] = {nn.x, nn.y, nn.z, nn.w};

        float* po = out + (b * OUT_CH + o) * LOUT;
        const int tb = t0 + 4 * u;
#pragma unroll
        for (int dt = 0; dt < 4; dt++) {
            int t = tb + dt;
            if (t < LOUT) po[t] = acc[dt] * __fdividef(1.0f, nv[dt]);
        }
    }
}

// ---------------------------------------------------------------------------
extern "C" void kernel_launch(void* const* d_in, const int* in_sizes, int n_in,
                              void* d_out, int out_size) {
    const float* x      = (const float*)d_in[0];   // (16, 4, 2048) f32
    const float* thetas = (const float*)d_in[1];   // (8, 2, 7, 3) f32
    float* out = (float*)d_out;                    // (16, 8, 2041) f32

    void* pC = nullptr;
    cudaGetSymbolAddress(&pC, c_B);

    dim3 bgrid(16, OUT_CH);                        // 128 blocks
    build_kernel<<<bgrid, 256>>>(thetas, (float*)pC);

    // conv with programmatic dependent launch: overlaps its prologue with build
    cudaLaunchConfig_t cfg = {};
    cfg.gridDim  = dim3((LOUT + TILE_T - 1) / TILE_T, BATCH, OUT_CH);  // 4x16x8
    cfg.blockDim = dim3(NTHR, 1, 1);
    cfg.dynamicSmemBytes = 0;
    cfg.stream = 0;
    cudaLaunchAttribute attr;
    attr.id = cudaLaunchAttributeProgrammaticStreamSerialization;
    attr.val.programmaticStreamSerializationAllowed = 1;
    cfg.attrs = &attr;
    cfg.numAttrs = 1;
    cudaLaunchKernelEx(&cfg, conv_kernel, x, out);
}

// round 17
// speedup vs baseline: 1.7352x; 1.0590x over previous
#include <cuda_runtime.h>
#include <cuda_bf16.h>
#include <math.h>

#define IN_CH    4
#define OUT_CH   8
#define KW       8
#define N_LAYERS 2
#define N_IN     32
#define N_QUBITS 7
#define QDIM     128
#define BATCH    16
#define LIN      2048
#define LOUT     (LIN - KW + 1)   // 2041
#define NGATES   (N_LAYERS * N_QUBITS)

// Quadratic-form matrices, symmetric-packed, in the constant bank:
//   B[o][i][j] = 0 (j<i), A_ii (j==i), 2*A_ij (j>i)
// build_kernel writes DIRECTLY to this symbol's device address.
__constant__ float4 c_B[OUT_CH * N_IN * N_IN / 4];

// ---------------------------------------------------------------------------
// build kernel: grid (16 i-groups, 8 out-ch) = 128 blocks, 256 threads.
// Each block simulates the 32 basis columns of its o, then computes 2 rows
// of A with 4 warps per row (32 m each, z0 sign folded), reducing in shared.
// Triggers PDL completion at start so conv can launch concurrently.
// ---------------------------------------------------------------------------
__global__ __launch_bounds__(256, 1)
void build_kernel(const float* __restrict__ thetas, float* __restrict__ cB) {
    __shared__ float sU[NGATES][8];
    __shared__ float2 sT[QDIM * 33];     // [m][j] (re,im)
    __shared__ float sP[8][33];          // per-warp partial rows

    if (threadIdx.x == 0) cudaTriggerProgrammaticLaunchCompletion();

    const int ig = blockIdx.x;           // rows 2*ig, 2*ig+1
    const int o  = blockIdx.y;
    const int tid  = threadIdx.x;
    const int warp = tid >> 5;
    const int lane = tid & 31;

    if (tid < NGATES) {
        const float* th = thetas + (o * NGATES + tid) * 3;
        float a = th[0], b = th[1], g = th[2];
        float sb, cb; __sincosf(0.5f * b, &sb, &cb);
        float sp, cp; __sincosf(0.5f * (a + g), &sp, &cp);   // ep
        float sm, cm; __sincosf(0.5f * (a - g), &sm, &cm);   // em
        sU[tid][0] =  cp * cb;  sU[tid][1] = -sp * cb;       // u00 = conj(ep)*cb
        sU[tid][2] = -cm * sb;  sU[tid][3] =  sm * sb;       // u01 = -conj(em)*sb
        sU[tid][4] =  cm * sb;  sU[tid][5] =  sm * sb;       // u10 = em*sb
        sU[tid][6] =  cp * cb;  sU[tid][7] =  sp * cb;       // u11 = ep*cb
    }
    __syncthreads();

    // warp simulates columns j = 4*warp + c; amps m = lane + 32*r.
    float re[4][4], im[4][4];
#pragma unroll
    for (int c = 0; c < 4; c++)
#pragma unroll
        for (int r = 0; r < 4; r++) { re[c][r] = 0.f; im[c][r] = 0.f; }
#pragma unroll
    for (int c = 0; c < 4; c++)
        if (lane == 4 * warp + c) re[c][0] = 1.0f;

    for (int l = 0; l < N_LAYERS; l++) {
#pragma unroll
        for (int q = 0; q < N_QUBITS; q++) {
            const float* U = sU[l * N_QUBITS + q];
            float u00r = U[0], u00i = U[1], u01r = U[2], u01i = U[3];
            float u10r = U[4], u10i = U[5], u11r = U[6], u11i = U[7];
            int p = 6 - q;
            if (p >= 5) {
                int d = 1 << (p - 5);
#pragma unroll
                for (int c = 0; c < 4; c++)
#pragma unroll
                    for (int r0 = 0; r0 < 4; r0++) {
                        if (r0 & d) continue;
                        int r1 = r0 | d;
                        float a0r = re[c][r0], a0i = im[c][r0];
                        float a1r = re[c][r1], a1i = im[c][r1];
                        re[c][r0] = u00r*a0r - u00i*a0i + u01r*a1r - u01i*a1i;
                        im[c][r0] = u00r*a0i + u00i*a0r + u01r*a1i + u01i*a1r;
                        re[c][r1] = u10r*a0r - u10i*a0i + u11r*a1r - u11i*a1i;
                        im[c][r1] = u10r*a0i + u10i*a0r + u11r*a1i + u11i*a1r;
                    }
            } else {
                int mask = 1 << p;
                int bit = (lane >> p) & 1;
#pragma unroll
                for (int c = 0; c < 4; c++)
#pragma unroll
                    for (int r = 0; r < 4; r++) {
                        float otr = __shfl_xor_sync(0xffffffffu, re[c][r], mask);
                        float oti = __shfl_xor_sync(0xffffffffu, im[c][r], mask);
                        float sr = re[c][r], si = im[c][r];
                        if (bit == 0) {
                            re[c][r] = u00r*sr - u00i*si + u01r*otr - u01i*oti;
                            im[c][r] = u00r*si + u00i*sr + u01r*oti + u01i*otr;
                        } else {
                            re[c][r] = u10r*otr - u10i*oti + u11r*sr - u11i*si;
                            im[c][r] = u10r*oti + u10i*otr + u11r*si + u11i*sr;
                        }
                    }
            }
        }
#pragma unroll
        for (int r = 0; r < 4; r++) {
            int m = lane + 32 * r;
            int k = __popc(m);
            if (((k * (k - 1)) >> 1) & 1) {
#pragma unroll
                for (int c = 0; c < 4; c++) { re[c][r] = -re[c][r]; im[c][r] = -im[c][r]; }
            }
        }
    }

#pragma unroll
    for (int c = 0; c < 4; c++) {
        int j = 4 * warp + c;
#pragma unroll
        for (int r = 0; r < 4; r++) {
            int m = lane + 32 * r;
            sT[m * 33 + j] = make_float2(re[c][r], im[c][r]);
        }
    }
    __syncthreads();

    // Phase C: warp w -> row r = w>>2, m-quarter q = w&3 (32 m each).
    {
        const int r  = warp >> 2;
        const int qm = (warp & 3) * 32;
        const int i  = ig * 2 + r;
        const int j  = lane;
        float s0 = 0.f, s1 = 0.f;
#pragma unroll
        for (int mm = 0; mm < 32; mm += 2) {
            int m = qm + mm;
            float2 ci0 = sT[m*33 + i],     cj0 = sT[m*33 + j];
            float2 ci1 = sT[(m+1)*33 + i], cj1 = sT[(m+1)*33 + j];
            s0 = __fmaf_rn(ci0.x, cj0.x, __fmaf_rn(ci0.y, cj0.y, s0));
            s1 = __fmaf_rn(ci1.x, cj1.x, __fmaf_rn(ci1.y, cj1.y, s1));
        }
        float s = s0 + s1;
        sP[warp][lane] = (qm < 64) ? s : -s;
    }
    __syncthreads();

    if (tid < 64) {
        const int r = tid >> 5, j = tid & 31;
        const int i = ig * 2 + r;
        float s = sP[4*r + 0][j] + sP[4*r + 1][j] + sP[4*r + 2][j] + sP[4*r + 3][j];
        float val = (j < i) ? 0.f : (j == i ? s : 2.f * s);
        cB[(o * N_IN + i) * N_IN + j] = val;
    }
}

// ---------------------------------------------------------------------------
// conv kernel (R13 frame): 256 threads; warp pair covers 32 t-quads.
// Phase split 72/72 j4-groups. Inner update is an explicit 4-FFMA chain
// (no separate FADD): 20% fewer fma-pipe ops than the tree+add form.
// PDL prologue (staging, unpack, norms) before cudaGridDependencySynchronize.
// ---------------------------------------------------------------------------
#define NTHR   256
#define TILE_T 512
#define XROW   520                 // 512 + KW, mult of 4 -> 16B-aligned rows

#define XV(j,dt) xv[(j) >> 3][((j) & 7) + (dt)]

__global__ __launch_bounds__(NTHR)
void conv_kernel(const float* __restrict__ x, float* __restrict__ out) {
    __shared__ alignas(16) float xs[IN_CH][XROW];
    __shared__ alignas(16) float4 sAcc[128];
    __shared__ alignas(16) float4 sN2[128];

    const int b  = blockIdx.y;
    const int o  = blockIdx.z;
    const int t0 = blockIdx.x * TILE_T;
    const int tid = threadIdx.x;

    for (int idx = tid; idx < IN_CH * (TILE_T + KW); idx += NTHR) {
        int c = idx / (TILE_T + KW), i = idx % (TILE_T + KW);
        int gi = t0 + i;
        xs[c][i] = (gi < LIN) ? x[(b * IN_CH + c) * LIN + gi] : 0.f;
    }
    __syncthreads();

    const int warp  = tid >> 5;
    const int lane  = tid & 31;
    const int u     = (warp >> 1) * 32 + lane;   // t-quad index 0..127
    const int phase = warp & 1;                  // warp-uniform

    // xv[c][0..10]: window for dt is w[c*8+k] = xv[c][k+dt], dt = 0..3
    float xv[IN_CH][12];
#pragma unroll
    for (int c = 0; c < IN_CH; c++) {
        const float4* xr = reinterpret_cast<const float4*>(&xs[c][4 * u]);
        float4 v0 = xr[0], v1 = xr[1], v2 = xr[2];
        xv[c][0]=v0.x; xv[c][1]=v0.y; xv[c][2] =v0.z; xv[c][3] =v0.w;
        xv[c][4]=v1.x; xv[c][5]=v1.y; xv[c][6] =v1.z; xv[c][7] =v1.w;
        xv[c][8]=v2.x; xv[c][9]=v2.y; xv[c][10]=v2.z; xv[c][11]=v2.w;
    }

    // window norms (independent of B) — phase0 computes them before the sync
    if (phase == 0) {
        float n2[4];
        float s = 0.f;
#pragma unroll
        for (int c = 0; c < IN_CH; c++)
#pragma unroll
            for (int k = 0; k < KW; k++) { float v = xv[c][k]; s = __fmaf_rn(v, v, s); }
        n2[0] = s;
#pragma unroll
        for (int dt = 1; dt < 4; dt++) {
            float d = 0.f;
#pragma unroll
            for (int c = 0; c < IN_CH; c++) {
                float vn = xv[c][dt + 7], vo = xv[c][dt - 1];
                d += vn * vn - vo * vo;
            }
            n2[dt] = n2[dt - 1] + d;
        }
        sN2[u] = make_float4(n2[0], n2[1], n2[2], n2[3]);
    }

    // wait for build_kernel (PDL): full completion + memory visibility
    cudaGridDependencySynchronize();

    const int obase = o * (N_IN * N_IN / 4);   // warp-uniform
    float acc[4] = {0.f, 0.f, 0.f, 0.f};

#define PROCESS_PAIR(ip_)                                                     \
    {                                                                         \
        const int ibq = (ip_) >> 1;                                           \
        float s0[4] = {0.f,0.f,0.f,0.f}, s1[4] = {0.f,0.f,0.f,0.f};           \
        _Pragma("unroll")                                                     \
        for (int j4 = ibq; j4 < 8; j4++) {                                    \
            float4 a0 = c_B[obase + (2*(ip_)    ) * 8 + j4];                  \
            float4 a1 = c_B[obase + (2*(ip_) + 1) * 8 + j4];                  \
            const int j0 = 4 * j4;                                            \
            _Pragma("unroll")                                                 \
            for (int dt = 0; dt < 4; dt++) {                                  \
                float w0 = XV(j0, dt),   w1 = XV(j0+1, dt);                   \
                float w2 = XV(j0+2, dt), w3 = XV(j0+3, dt);                   \
                s0[dt] = __fmaf_rn(a0.x, w0, __fmaf_rn(a0.y, w1,              \
                         __fmaf_rn(a0.z, w2, __fmaf_rn(a0.w, w3, s0[dt]))));  \
                s1[dt] = __fmaf_rn(a1.x, w0, __fmaf_rn(a1.y, w1,              \
                         __fmaf_rn(a1.z, w2, __fmaf_rn(a1.w, w3, s1[dt]))));  \
            }                                                                 \
        }                                                                     \
        _Pragma("unroll")                                                     \
        for (int dt = 0; dt < 4; dt++) {                                      \
            acc[dt] = __fmaf_rn(s0[dt], XV(2*(ip_),     dt), acc[dt]);        \
            acc[dt] = __fmaf_rn(s1[dt], XV(2*(ip_) + 1, dt), acc[dt]);        \
        }                                                                     \
    }

    if (phase == 0) {
#pragma unroll
        for (int ip = 0; ip < 5; ip++) PROCESS_PAIR(ip)
        sAcc[u] = make_float4(acc[0], acc[1], acc[2], acc[3]);
    } else {
#pragma unroll
        for (int ip = 5; ip < 16; ip++) PROCESS_PAIR(ip)
    }

    __syncthreads();

    if (phase == 1) {
        float4 p  = sAcc[u];
        float4 nn = sN2[u];
        acc[0] += p.x; acc[1] += p.y; acc[2] += p.z; acc[3] += p.w;
        float nv[4] = {nn.x, nn.y, nn.z, nn.w};

        float* po = out + (b * OUT_CH + o) * LOUT;
        const int tb = t0 + 4 * u;
#pragma unroll
        for (int dt = 0; dt < 4; dt++) {
            int t = tb + dt;
            if (t < LOUT) po[t] = acc[dt] * __fdividef(1.0f, nv[dt]);
        }
    }
}

// ---------------------------------------------------------------------------
extern "C" void kernel_launch(void* const* d_in, const int* in_sizes, int n_in,
                              void* d_out, int out_size) {
    const float* x      = (const float*)d_in[0];   // (16, 4, 2048) f32
    const float* thetas = (const float*)d_in[1];   // (8, 2, 7, 3) f32
    float* out = (float*)d_out;                    // (16, 8, 2041) f32

    void* pC = nullptr;
    cudaGetSymbolAddress(&pC, c_B);

    dim3 bgrid(16, OUT_CH);                        // 128 blocks
    build_kernel<<<bgrid, 256>>>(thetas, (float*)pC);

    // conv with programmatic dependent launch: overlaps its prologue with build
    cudaLaunchConfig_t cfg = {};
    cfg.gridDim  = dim3((LOUT + TILE_T - 1) / TILE_T, BATCH, OUT_CH);  // 4x16x8
    cfg.blockDim = dim3(NTHR, 1, 1);
    cfg.dynamicSmemBytes = 0;
    cfg.stream = 0;
    cudaLaunchAttribute attr;
    attr.id = cudaLaunchAttributeProgrammaticStreamSerialization;
    attr.val.programmaticStreamSerializationAllowed = 1;
    cfg.attrs = &attr;
    cfg.numAttrs = 1;
    cudaLaunchKernelEx(&cfg, conv_kernel, x, out);
}